// round 6
// baseline (speedup 1.0000x reference)
#include <cuda_runtime.h>
#include <math.h>

#define GRP 64
#define MN  128
#define NNODES (GRP*MN)
#define NRAD 16
#define SPT 2              // radials per thread
#define SCHUNKS (NRAD/SPT) // 8
#define JSPLIT 2
#define JCHUNK (MN/JSPLIT) // 64

__device__ __forceinline__ float rcp_approx(float x) {
    float r; asm("rcp.approx.f32 %0, %1;" : "=f"(r) : "f"(x)); return r;
}

__global__ void zero_feats_kernel(float* __restrict__ out) {
    // zero the features region: NNODES*64 floats = 131072 float4
    int idx = blockIdx.x * blockDim.x + threadIdx.x;
    ((float4*)out)[idx] = make_float4(0.f, 0.f, 0.f, 0.f);
}

__global__ __launch_bounds__(MN, 8)
void rsaef_kernel(const float* __restrict__ sf,   // (N,4)
                  const float* __restrict__ pos,  // (N,3)
                  float* __restrict__ out)        // features (N,64) then si (N,64)
{
    __shared__ float4 sh_pq[MN];  // pos.xyz, q
    __shared__ float4 sh_mu[MN];  // mu = sf[:, {3,1,2}]

    const int g    = blockIdx.x;
    const int sc   = blockIdx.y;
    const int half = blockIdx.z;
    const int i    = threadIdx.x;
    const int node = g * MN + i;

    // cooperative load of this group's nodes into smem
    {
        const float* p = pos + (size_t)g * MN * 3;
        const float* f = sf  + (size_t)g * MN * 4;
        float4 pq;
        pq.x = p[i*3+0]; pq.y = p[i*3+1]; pq.z = p[i*3+2];
        pq.w = f[i*4+0];
        sh_pq[i] = pq;
        float4 mu;
        mu.x = f[i*4+3]; mu.y = f[i*4+1]; mu.z = f[i*4+2]; mu.w = 0.f;
        sh_mu[i] = mu;
    }
    __syncthreads();

    // per-thread radial constants, computed in double to match numpy f64 -> f32
    const double PI  = 3.14159265358979323846;
    const double KCd = 14.399645351950548;
    const double ISQPI = 0.5641895835477562869480794515607725858;
    float wv[SPT], halfinvw[SPT], ginv[SPT], inv2w2[SPT], l0f[SPT], l1w[SPT];
    #pragma unroll
    for (int t = 0; t < SPT; t++) {
        int k = sc * SPT + t;
        double sig = 0.5 + (double)k * (2.5 / 15.0);
        double w   = sqrt((1.0 + sig*sig) * 0.5);
        double pi15 = pow(PI, 1.5);
        double s3 = sig*sig*sig;
        double s5 = s3*sig*sig;
        double cl0rec  = 1.0 / sqrt(pi15 * s3);
        double cl0mult = 1.0 / (pow(2.0*PI, 1.5) * s3);
        double cl1rec  = 1.0 / sqrt(pi15 * s5 * 3.0 / 2.0);
        double L0F = cl0rec / cl0mult;
        double L1W = sqrt(3.0) * sig * sig * cl1rec / cl0mult;
        wv[t]       = (float)w;
        halfinvw[t] = (float)(0.5 / w);
        ginv[t]     = (float)(ISQPI / w);
        inv2w2[t]   = (float)(1.0 / (2.0 * w * w));
        l0f[t]      = (float)(KCd * L0F);
        l1w[t]      = (float)(KCd * L1W);
    }
    const float INV_SQRT_PI = 0.56418958354775628695f;

    const float4 me = sh_pq[i];

    float acc0[SPT], a1x[SPT], a1y[SPT], a1z[SPT];
    #pragma unroll
    for (int t = 0; t < SPT; t++) { acc0[t]=0.f; a1x[t]=0.f; a1y[t]=0.f; a1z[t]=0.f; }

    const int jbeg = half * JCHUNK;
    #pragma unroll 4
    for (int q = 0; q < JCHUNK; q++) {
        const int j = jbeg + q;
        float4 pj  = sh_pq[j];
        float4 muj = sh_mu[j];
        float mask = (j == i) ? 0.f : 1.f;
        float qj = pj.w * mask;
        float mx = muj.x * mask, my = muj.y * mask, mz = muj.z * mask;

        float Rx = me.x - pj.x, Ry = me.y - pj.y, Rz = me.z - pj.z;
        float r2 = fmaf(Rx, Rx, fmaf(Ry, Ry, Rz*Rz));
        r2 = fmaxf(r2, 1e-20f);
        float inv_r  = rsqrtf(r2);
        float r      = r2 * inv_r;
        float hx = Rx * inv_r, hy = Ry * inv_r, hz = Rz * inv_r;
        float muR = fmaf(mx, hx, fmaf(my, hy, mz * hz));

        #pragma unroll
        for (int t = 0; t < SPT; t++) {
            float u    = r * halfinvw[t];
            float e    = __expf(-u * u);
            // branchless erf (A&S 7.1.26), reuses e; abs err <= 1.5e-7
            float d    = fmaf(0.3275911f, u, 1.0f);
            float tt   = rcp_approx(d);
            float P    = fmaf(1.061405429f, tt, -1.453152027f);
            P = fmaf(P, tt, 1.421413741f);
            P = fmaf(P, tt, -0.284496736f);
            P = fmaf(P, tt, 0.254829592f);
            float erfu = fmaf(-(P * tt), e, 1.0f);

            float gg   = e * ginv[t];
            float T    = erfu * inv_r;
            float fp   = (gg - T) * inv_r;
            float fpor = fp * inv_r;
            // fpp = -gg*inv2w2 - 2*fpor  =>  fpor - fpp = 3*fpor + gg*inv2w2
            float coef = muR * fmaf(gg, inv2w2[t], 3.0f * fpor);
            float A    = fmaf(fp, qj, coef);

            acc0[t] = fmaf(qj, T, fmaf(-muR, fp, acc0[t]));
            a1x[t]  = fmaf(A, hx, fmaf(-fpor, mx, a1x[t]));
            a1y[t]  = fmaf(A, hy, fmaf(-fpor, my, a1y[t]));
            a1z[t]  = fmaf(A, hz, fmaf(-fpor, mz, a1z[t]));
        }
    }

    // accumulate pre-scaled partial sums into features (collision degree = 2)
    float* frow = out + (size_t)node * 64;
    #pragma unroll
    for (int t = 0; t < SPT; t++) {
        int k = sc * SPT + t;
        atomicAdd(&frow[k],            l0f[t] * acc0[t]);
        atomicAdd(&frow[16 + 3*k + 0], l1w[t] * a1y[t]);  // component 1
        atomicAdd(&frow[16 + 3*k + 1], l1w[t] * a1z[t]);  // component 2
        atomicAdd(&frow[16 + 3*k + 2], l1w[t] * a1x[t]);  // component 0
    }

    // self-interaction terms: written once (half==1), plain stores
    if (half == 1) {
        float* srow = out + (size_t)NNODES * 64 + (size_t)node * 64;
        const float* f = sf + (size_t)node * 4;
        float q = f[0], m1 = f[1], m2 = f[2], m3 = f[3];
        #pragma unroll
        for (int t = 0; t < SPT; t++) {
            int k = sc * SPT + t;
            float si0 = l0f[t] * q * (2.0f * halfinvw[t]) * INV_SQRT_PI;
            float w3  = wv[t] * wv[t] * wv[t];
            float sic = l1w[t] * (1.f / (6.f * w3)) * INV_SQRT_PI;
            srow[k]            = si0;
            srow[16 + 3*k + 0] = sic * m1;
            srow[16 + 3*k + 1] = sic * m2;
            srow[16 + 3*k + 2] = sic * m3;
        }
    }
}

extern "C" void kernel_launch(void* const* d_in, const int* in_sizes, int n_in,
                              void* d_out, int out_size)
{
    const float* sf  = (const float*)d_in[0];  // source_feats (N,4)
    const float* pos = (const float*)d_in[1];  // node_positions (N,3)
    float* out = (float*)d_out;

    // zero the features accumulation region (NNODES*64 floats)
    zero_feats_kernel<<<(NNODES * 64 / 4 + 255) / 256, 256>>>(out);

    dim3 grid(GRP, SCHUNKS, JSPLIT);
    rsaef_kernel<<<grid, MN>>>(sf, pos, out);
}

// round 7
// speedup vs baseline: 2.7948x; 2.7948x over previous
#include <cuda_runtime.h>
#include <math.h>

#define GRP 64
#define MN  128
#define NNODES (GRP*MN)
#define NRAD 16
#define SPT 2              // radials per thread
#define SCHUNKS (NRAD/SPT) // 8

struct RadConsts {
    float halfinvw[NRAD];
    float ginv[NRAD];
    float inv2w2[NRAD];
    float l0f[NRAD];
    float l1w[NRAD];
    float si0[NRAD];
    float si1[NRAD];
};

__device__ __forceinline__ float rcp_approx(float x) {
    float r; asm("rcp.approx.f32 %0, %1;" : "=f"(r) : "f"(x)); return r;
}

__global__ __launch_bounds__(MN, 8)
void rsaef_kernel(const float* __restrict__ sf,   // (N,4)
                  const float* __restrict__ pos,  // (N,3)
                  float* __restrict__ out,        // features (N,64) then si (N,64)
                  const RadConsts rc)
{
    __shared__ float4 sh_pq[MN];  // pos.xyz, q
    __shared__ float4 sh_mu[MN];  // mu = sf[:, {3,1,2}]

    const int g  = blockIdx.x;
    const int sc = blockIdx.y;
    const int i  = threadIdx.x;
    const int node = g * MN + i;

    // cooperative load of this group's nodes into smem
    {
        const float* p = pos + (size_t)g * MN * 3;
        const float* f = sf  + (size_t)g * MN * 4;
        float4 pq;
        pq.x = p[i*3+0]; pq.y = p[i*3+1]; pq.z = p[i*3+2];
        pq.w = f[i*4+0];
        sh_pq[i] = pq;
        float4 mu;
        mu.x = f[i*4+3]; mu.y = f[i*4+1]; mu.z = f[i*4+2]; mu.w = 0.f;
        sh_mu[i] = mu;
    }
    __syncthreads();

    // per-thread radial constants: straight from the param struct (LDC, no FP64)
    float halfinvw[SPT], ginv[SPT], inv2w2[SPT], l0f[SPT], l1w[SPT];
    #pragma unroll
    for (int t = 0; t < SPT; t++) {
        int k = sc * SPT + t;
        halfinvw[t] = rc.halfinvw[k];
        ginv[t]     = rc.ginv[k];
        inv2w2[t]   = rc.inv2w2[k];
        l0f[t]      = rc.l0f[k];
        l1w[t]      = rc.l1w[k];
    }

    const float4 me = sh_pq[i];

    float acc0[SPT], a1x[SPT], a1y[SPT], a1z[SPT];
    #pragma unroll
    for (int t = 0; t < SPT; t++) { acc0[t]=0.f; a1x[t]=0.f; a1y[t]=0.f; a1z[t]=0.f; }

    #pragma unroll 4
    for (int j = 0; j < MN; j++) {
        float4 pj  = sh_pq[j];
        float4 muj = sh_mu[j];
        float mask = (j == i) ? 0.f : 1.f;
        float qj = pj.w * mask;
        float mx = muj.x * mask, my = muj.y * mask, mz = muj.z * mask;

        float Rx = me.x - pj.x, Ry = me.y - pj.y, Rz = me.z - pj.z;
        float r2 = fmaf(Rx, Rx, fmaf(Ry, Ry, Rz*Rz));
        r2 = fmaxf(r2, 1e-20f);
        float inv_r  = rsqrtf(r2);
        float r      = r2 * inv_r;
        float hx = Rx * inv_r, hy = Ry * inv_r, hz = Rz * inv_r;
        float muR = fmaf(mx, hx, fmaf(my, hy, mz * hz));

        #pragma unroll
        for (int t = 0; t < SPT; t++) {
            float u    = r * halfinvw[t];
            float e    = __expf(-u * u);
            // branchless erf (A&S 7.1.26), reuses e; abs err <= 1.5e-7
            float d    = fmaf(0.3275911f, u, 1.0f);
            float tt   = rcp_approx(d);
            float P    = fmaf(1.061405429f, tt, -1.453152027f);
            P = fmaf(P, tt, 1.421413741f);
            P = fmaf(P, tt, -0.284496736f);
            P = fmaf(P, tt, 0.254829592f);
            float erfu = fmaf(-(P * tt), e, 1.0f);

            float gg   = e * ginv[t];
            float T    = erfu * inv_r;
            float fp   = (gg - T) * inv_r;
            float fpor = fp * inv_r;
            // fpp = -gg*inv2w2 - 2*fpor  =>  fpor - fpp = 3*fpor + gg*inv2w2
            float coef = muR * fmaf(gg, inv2w2[t], 3.0f * fpor);
            float A    = fmaf(fp, qj, coef);

            acc0[t] = fmaf(qj, T, fmaf(-muR, fp, acc0[t]));
            a1x[t]  = fmaf(A, hx, fmaf(-fpor, mx, a1x[t]));
            a1y[t]  = fmaf(A, hy, fmaf(-fpor, my, a1y[t]));
            a1z[t]  = fmaf(A, hz, fmaf(-fpor, mz, a1z[t]));
        }
    }

    // features row: [l0 (16)] [l1 (16 x 3), component perm (1,2,0)]
    float* frow = out + (size_t)node * 64;
    #pragma unroll
    for (int t = 0; t < SPT; t++) {
        int k = sc * SPT + t;
        frow[k]              = l0f[t] * acc0[t];
        frow[16 + 3*k + 0]   = l1w[t] * a1y[t];  // component 1
        frow[16 + 3*k + 1]   = l1w[t] * a1z[t];  // component 2
        frow[16 + 3*k + 2]   = l1w[t] * a1x[t];  // component 0
    }

    // self-interaction terms: si (N,64) after features
    float* srow = out + (size_t)NNODES * 64 + (size_t)node * 64;
    const float* f = sf + (size_t)node * 4;
    float q = f[0], m1 = f[1], m2 = f[2], m3 = f[3];
    #pragma unroll
    for (int t = 0; t < SPT; t++) {
        int k = sc * SPT + t;
        srow[k]            = rc.si0[k] * q;
        srow[16 + 3*k + 0] = rc.si1[k] * m1;
        srow[16 + 3*k + 1] = rc.si1[k] * m2;
        srow[16 + 3*k + 2] = rc.si1[k] * m3;
    }
}

static RadConsts make_consts() {
    RadConsts rc;
    const double PI  = 3.14159265358979323846;
    const double KCd = 14.399645351950548;
    const double ISQPI = 0.5641895835477562869480794515607725858;
    for (int k = 0; k < NRAD; k++) {
        double sig = 0.5 + (double)k * (2.5 / 15.0);
        double w   = sqrt((1.0 + sig*sig) * 0.5);
        double pi15 = pow(PI, 1.5);
        double s3 = sig*sig*sig;
        double s5 = s3*sig*sig;
        double cl0rec  = 1.0 / sqrt(pi15 * s3);
        double cl0mult = 1.0 / (pow(2.0*PI, 1.5) * s3);
        double cl1rec  = 1.0 / sqrt(pi15 * s5 * 3.0 / 2.0);
        double L0F = cl0rec / cl0mult;
        double L1W = sqrt(3.0) * sig * sig * cl1rec / cl0mult;
        rc.halfinvw[k] = (float)(0.5 / w);
        rc.ginv[k]     = (float)(ISQPI / w);
        rc.inv2w2[k]   = (float)(1.0 / (2.0 * w * w));
        rc.l0f[k]      = (float)(KCd * L0F);
        rc.l1w[k]      = (float)(KCd * L1W);
        rc.si0[k]      = (float)(KCd * L0F * ISQPI / w);
        rc.si1[k]      = (float)(KCd * L1W / (6.0 * w * w * w) * ISQPI);
    }
    return rc;
}

extern "C" void kernel_launch(void* const* d_in, const int* in_sizes, int n_in,
                              void* d_out, int out_size)
{
    const float* sf  = (const float*)d_in[0];  // source_feats (N,4)
    const float* pos = (const float*)d_in[1];  // node_positions (N,3)
    float* out = (float*)d_out;

    static const RadConsts rc = make_consts();  // host-side, FP64, once

    dim3 grid(GRP, SCHUNKS);
    rsaef_kernel<<<grid, MN>>>(sf, pos, out, rc);
}